// round 16
// baseline (speedup 1.0000x reference)
#include <cuda_runtime.h>
#include <cuda_bf16.h>
#include <cuda_fp16.h>
#include <math.h>
#include <stdint.h>

#define Nn 100000
#define Ee 300000
#define Hh 256
#define Cc 40
#define Ll 6
#define FIN 128
#define BN_EPS 1e-5f

// ---------------- device scratch ----------------
__device__ __half g_hw[Nn * Hh];
__device__ __half g_agg[Nn * Hh];
__device__ __half g_xin[Nn * Hh];
__device__ __half g_ap[Ll - 1][Nn * Hh];
__device__ __half g_a[Nn * Hh];
__device__ __half g_xq[Nn * FIN];
#define BT_IN_OFF 0
#define BT_CONV_OFF (Hh * FIN)
__device__ __half g_bt[Hh * FIN + Ll * Hh * Hh];
__device__ float g_dinv[Nn];
__device__ int   g_deg[Nn];
__device__ int   g_cursor[Nn];
__device__ int   g_rowoff[Nn + 1];
__device__ int2  g_csr[Ee];
__device__ double g_bsum[Ll][Hh];
__device__ double g_bsq[Ll][Hh];
__device__ int    g_aggdone[Ll];
__device__ float g_mean[Hh];
__device__ float g_rstd[Hh];
__device__ float g_cm[Ll];
__device__ float g_xc;
__device__ int   g_bsums_scan[256];

// ---------------- helpers ----------------
__device__ __forceinline__ uint32_t smem_u32(const void* p) {
    uint32_t a;
    asm("{ .reg .u64 t; cvta.to.shared.u64 t, %1; cvt.u32.u64 %0, t; }" : "=r"(a) : "l"(p));
    return a;
}
__device__ __forceinline__ void cpasync16(uint32_t dst, const void* src, int szbytes) {
    asm volatile("cp.async.cg.shared.global [%0], [%1], 16, %2;"
                 :: "r"(dst), "l"(src), "r"(szbytes) : "memory");
}
#define CP_COMMIT() asm volatile("cp.async.commit_group;" ::: "memory")
#define CP_WAIT(n)  asm volatile("cp.async.wait_group %0;" :: "n"(n) : "memory")

__device__ __forceinline__ void ldsm4(uint32_t& r0, uint32_t& r1, uint32_t& r2, uint32_t& r3, uint32_t addr) {
    asm volatile("ldmatrix.sync.aligned.m8n8.x4.shared.b16 {%0,%1,%2,%3}, [%4];"
                 : "=r"(r0), "=r"(r1), "=r"(r2), "=r"(r3) : "r"(addr));
}
__device__ __forceinline__ void mma_f16(float c[4], const uint32_t a[4], uint32_t b0, uint32_t b1) {
    asm volatile("mma.sync.aligned.m16n8k16.row.col.f32.f16.f16.f32 "
                 "{%0,%1,%2,%3}, {%4,%5,%6,%7}, {%8,%9}, {%0,%1,%2,%3};"
                 : "+f"(c[0]), "+f"(c[1]), "+f"(c[2]), "+f"(c[3])
                 : "r"(a[0]), "r"(a[1]), "r"(a[2]), "r"(a[3]), "r"(b0), "r"(b1));
}

// ---------------- fp16 GEMM, 3 CTAs/SM, compile-time K ----------------
#define ST_SZ   12288
#define SM_B    8192
#define SMEM_DYN (3 * ST_SZ)

template<int KK>
__global__ void __launch_bounds__(256, 3)
k_gemm(const __half* __restrict__ A, const __half* __restrict__ B,
       const float* __restrict__ bias, __half* __restrict__ C,
       __half* __restrict__ C2, int M)
{
    extern __shared__ char smem[];
    uint32_t sb = smem_u32(smem);
    int tid = threadIdx.x;
    int lane = tid & 31, wid = tid >> 5;
    int wm = wid >> 1, wn = wid & 1;
    int row0 = blockIdx.y * 128;
    int nb0 = blockIdx.x * 64;
    constexpr int nc = KK >> 5;

    const char* AC = (const char*)A;
    const char* BC = (const char*)B;

    float c[2][4][4];
#pragma unroll
    for (int mt = 0; mt < 2; mt++)
#pragma unroll
        for (int nt = 0; nt < 4; nt++)
#pragma unroll
            for (int j = 0; j < 4; j++) c[mt][nt][j] = 0.f;

    auto stage_load = [&](int s, int kc) {
        uint32_t so = sb + s * ST_SZ;
#pragma unroll
        for (int j = 0; j < 2; j++) {
            int flat = tid + j * 256;
            int row = flat >> 2, cq = flat & 3;
            int grow = row0 + row;
            int sz = (grow < M) ? 16 : 0;
            int gc = (grow < M) ? grow : (M - 1);
            size_t srcoff = ((size_t)gc * KK + kc * 32 + cq * 8) * 2;
            uint32_t dst = so + row * 64 + ((cq ^ ((row >> 1) & 3)) << 4);
            cpasync16(dst, AC + srcoff, sz);
        }
        {
            int n = tid >> 2, cq = tid & 3;
            size_t srcoff = ((size_t)(nb0 + n) * KK + kc * 32 + cq * 8) * 2;
            uint32_t dst = so + SM_B + n * 64 + ((cq ^ ((n >> 1) & 3)) << 4);
            cpasync16(dst, BC + srcoff, 16);
        }
    };

    stage_load(0, 0);
    CP_COMMIT();
    if (nc > 1) { stage_load(1, 1); CP_COMMIT(); }

    for (int kc = 0; kc < nc; kc++) {
        if (kc + 2 < nc) {
            stage_load((kc + 2) % 3, kc + 2);
            CP_COMMIT();
            CP_WAIT(2);
        } else {
            CP_WAIT(0);
        }
        __syncthreads();

        uint32_t so = sb + (kc % 3) * ST_SZ;
#pragma unroll
        for (int ks = 0; ks < 2; ks++) {
            uint32_t ah[2][4];
#pragma unroll
            for (int mt = 0; mt < 2; mt++) {
                int ml = wm * 32 + mt * 16 + (lane & 7) + ((lane >> 3) & 1) * 8;
                int ck = 2 * ks + (lane >> 4);
                uint32_t ab = so + ml * 64 + ((ck ^ ((ml >> 1) & 3)) << 4);
                ldsm4(ah[mt][0], ah[mt][1], ah[mt][2], ah[mt][3], ab);
            }
            uint32_t bh[2][4];
#pragma unroll
            for (int j = 0; j < 2; j++) {
                int nl = wn * 32 + j * 16 + (lane & 7) + ((lane >> 4) << 3);
                int ck = 2 * ks + ((lane >> 3) & 1);
                uint32_t bb = so + SM_B + nl * 64 + ((ck ^ ((nl >> 1) & 3)) << 4);
                ldsm4(bh[j][0], bh[j][1], bh[j][2], bh[j][3], bb);
            }
#pragma unroll
            for (int j = 0; j < 2; j++) {
                int nb = j * 2;
#pragma unroll
                for (int mt = 0; mt < 2; mt++) {
                    mma_f16(c[mt][nb + 0], ah[mt], bh[j][0], bh[j][1]);
                    mma_f16(c[mt][nb + 1], ah[mt], bh[j][2], bh[j][3]);
                }
            }
        }
        __syncthreads();
    }

#pragma unroll
    for (int mt = 0; mt < 2; mt++) {
        int r = row0 + wm * 32 + mt * 16 + (lane >> 2);
#pragma unroll
        for (int nt = 0; nt < 4; nt++) {
            int col = nb0 + wn * 32 + nt * 8 + ((lane & 3) << 1);
            float v0 = c[mt][nt][0], v1 = c[mt][nt][1];
            float v2 = c[mt][nt][2], v3 = c[mt][nt][3];
            if (bias) {
                float b0 = bias[col], b1 = bias[col + 1];
                v0 += b0; v1 += b1; v2 += b0; v3 += b1;
            }
            if (r < M) {
                size_t o = (size_t)r * Hh + col;
                __half2 hv = __floats2half2_rn(v0, v1);
                *reinterpret_cast<__half2*>(&C[o]) = hv;
                if (C2) *reinterpret_cast<__half2*>(&C2[o]) = hv;
            }
            if (r + 8 < M) {
                size_t o = (size_t)(r + 8) * Hh + col;
                __half2 hv = __floats2half2_rn(v2, v3);
                *reinterpret_cast<__half2*>(&C[o]) = hv;
                if (C2) *reinterpret_cast<__half2*>(&C2[o]) = hv;
            }
        }
    }
}

// ---------------- splits ----------------
__global__ void k_split_w(const float* __restrict__ W, __half* __restrict__ dst, int K)
{
    int idx = blockIdx.x * 256 + threadIdx.x;
    if (idx >= Hh * K) return;
    int n = idx / K, k = idx - n * K;
    dst[idx] = __float2half(W[(size_t)k * Hh + n]);
}

__global__ void k_split_wconv(const float* __restrict__ W)
{
    int idx = blockIdx.x * 256 + threadIdx.x;
    if (idx >= Ll * Hh * Hh) return;
    int l = idx >> 16;
    int r = idx & 65535;
    int n = r >> 8, k = r & 255;
    g_bt[BT_CONV_OFF + idx] = __float2half(W[(size_t)l * Hh * Hh + (size_t)k * Hh + n]);
}

__global__ void k_split_x(const float* __restrict__ x)
{
    int idx = blockIdx.x * 256 + threadIdx.x;
    if (idx >= Nn * FIN) return;
    g_xq[idx] = __float2half(x[idx]);
}

// ---------------- setup kernels ----------------
__global__ void k_zero_deg() {
    int i = blockIdx.x * blockDim.x + threadIdx.x;
    if (i < Nn) { g_deg[i] = 0; g_cursor[i] = 0; }
}
__global__ void k_count(const int* __restrict__ ei) {
    int e = blockIdx.x * blockDim.x + threadIdx.x;
    if (e < Ee) atomicAdd(&g_deg[ei[Ee + e]], 1);
}
__global__ void k_dinv() {
    int i = blockIdx.x * blockDim.x + threadIdx.x;
    if (i < Nn) g_dinv[i] = rsqrtf((float)(g_deg[i] + 1));
}
__global__ void k_scan1() {
    __shared__ int s[512];
    int i = blockIdx.x * 512 + threadIdx.x;
    int v = (i < Nn) ? g_deg[i] : 0;
    s[threadIdx.x] = v;
    __syncthreads();
    int x = v;
#pragma unroll
    for (int off = 1; off < 512; off <<= 1) {
        int t = (threadIdx.x >= off) ? s[threadIdx.x - off] : 0;
        __syncthreads();
        x += t;
        s[threadIdx.x] = x;
        __syncthreads();
    }
    if (i < Nn) g_rowoff[i] = x - v;
    if (threadIdx.x == 511) g_bsums_scan[blockIdx.x] = x;
}
__global__ void k_scan2(int nb) {
    int acc = 0;
    for (int b = 0; b < nb; b++) { int t = g_bsums_scan[b]; g_bsums_scan[b] = acc; acc += t; }
    g_rowoff[Nn] = acc;
}
__global__ void k_scan3() {
    int i = blockIdx.x * 512 + threadIdx.x;
    if (i < Nn) g_rowoff[i] += g_bsums_scan[blockIdx.x];
}
__global__ void k_scatter(const int* __restrict__ ei) {
    int e = blockIdx.x * blockDim.x + threadIdx.x;
    if (e < Ee) {
        int s = ei[e];
        int d = ei[Ee + e];
        int pos = g_rowoff[d] + atomicAdd(&g_cursor[d], 1);
        float nr = g_dinv[s] * g_dinv[d];
        g_csr[pos] = make_int2(s, __float_as_int(nr));
    }
}
__global__ void k_softmax_w(const float* __restrict__ rw) {
    float mx = -1e30f;
    for (int l = 0; l < Ll; l++) mx = fmaxf(mx, rw[l]);
    float s = 0.f;
    float w[Ll];
    for (int l = 0; l < Ll; l++) { w[l] = expf(rw[l] - mx); s += w[l]; }
    for (int l = 0; l < Ll; l++) w[l] /= s;
    float csum = 0.f;
    for (int m = 0; m < Ll; m++) {
        float c = 0.f, p = 1.f;
        for (int l = m; l < Ll; l++) { c += w[l] * p; p *= 0.7f; }
        g_cm[m] = c;
        csum += c;
    }
    g_xc = 0.2f * csum;
}

// ---------------- aggregation: ONE node per warp (4x more latency chains) ----------------
__global__ void __launch_bounds__(256)
k_aggregate(const __half* __restrict__ hw, const float* __restrict__ cb, int layer)
{
    __shared__ float ssum[Hh], ssq[Hh];
    ssum[threadIdx.x] = 0.f;
    ssq[threadIdx.x] = 0.f;
    __syncthreads();

    int warp = threadIdx.x >> 5, lane = threadIdx.x & 31;
    float tsum[8], tsq[8];
#pragma unroll
    for (int k = 0; k < 8; k++) { tsum[k] = 0.f; tsq[k] = 0.f; }

    float cbv[8];
#pragma unroll
    for (int j = 0; j < 4; j++) {
        int col = 2 * (lane + 32 * j);
        cbv[2 * j] = cb[col];
        cbv[2 * j + 1] = cb[col + 1];
    }

    int i = blockIdx.x * 8 + warp;
    if (i < Nn) {
        float di = g_dinv[i];
        __half2 ws2 = __float2half2_rn(di * di);
        const __half2* hrow = reinterpret_cast<const __half2*>(hw + (size_t)i * Hh);
        __half2 acc[4];
#pragma unroll
        for (int j = 0; j < 4; j++)
            acc[j] = __hmul2(ws2, hrow[lane + 32 * j]);
        int e0 = g_rowoff[i], e1 = g_rowoff[i + 1];
        for (int e = e0; e < e1; e++) {
            int2 p = g_csr[e];
            int s = p.x;
            __half2 nr2 = __float2half2_rn(__int_as_float(p.y));
            const __half2* srow = reinterpret_cast<const __half2*>(hw + (size_t)s * Hh);
#pragma unroll
            for (int j = 0; j < 4; j++)
                acc[j] = __hfma2(nr2, srow[lane + 32 * j], acc[j]);
        }
        __half2* arow = reinterpret_cast<__half2*>(g_agg + (size_t)i * Hh);
#pragma unroll
        for (int j = 0; j < 4; j++) {
            float2 f = __half22float2(acc[j]);
            float v0 = f.x + cbv[2 * j];
            float v1 = f.y + cbv[2 * j + 1];
            arow[lane + 32 * j] = __floats2half2_rn(v0, v1);
            tsum[2 * j] += v0;  tsq[2 * j] += v0 * v0;
            tsum[2 * j + 1] += v1;  tsq[2 * j + 1] += v1 * v1;
        }
    }
#pragma unroll
    for (int j = 0; j < 4; j++) {
        int col = 2 * (lane + 32 * j);
        atomicAdd(&ssum[col], tsum[2 * j]);
        atomicAdd(&ssq[col], tsq[2 * j]);
        atomicAdd(&ssum[col + 1], tsum[2 * j + 1]);
        atomicAdd(&ssq[col + 1], tsq[2 * j + 1]);
    }
    __syncthreads();
    atomicAdd(&g_bsum[layer][threadIdx.x], (double)ssum[threadIdx.x]);
    atomicAdd(&g_bsq[layer][threadIdx.x], (double)ssq[threadIdx.x]);
    __threadfence();
    __syncthreads();

    __shared__ int isLast;
    if (threadIdx.x == 0)
        isLast = (atomicAdd(&g_aggdone[layer], 1) == (int)gridDim.x - 1);
    __syncthreads();
    if (isLast) {
        __threadfence();
        int c = threadIdx.x;
        double m = g_bsum[layer][c] / (double)Nn;
        double v = g_bsq[layer][c] / (double)Nn - m * m;
        g_mean[c] = (float)m;
        g_rstd[c] = (float)(1.0 / sqrt(v + (double)BN_EPS));
        g_bsum[layer][c] = 0.0;
        g_bsq[layer][c] = 0.0;
        if (c == 0) g_aggdone[layer] = 0;
    }
}

// ---------------- BN + ReLU + residual (layers 0..4) ----------------
__global__ void __launch_bounds__(256)
k_bnapply(const float* __restrict__ gamma, const float* __restrict__ beta,
          int layer, float prevCoef)
{
    int idx = blockIdx.x * blockDim.x + threadIdx.x;
    if (idx >= Nn * (Hh / 4)) return;
    int c4 = (idx & 63);
    uint2 araw = reinterpret_cast<const uint2*>(g_agg)[idx];
    float2 a01 = __half22float2(*reinterpret_cast<__half2*>(&araw.x));
    float2 a23 = __half22float2(*reinterpret_cast<__half2*>(&araw.y));
    float4 mn = reinterpret_cast<const float4*>(g_mean)[c4];
    float4 rs = reinterpret_cast<const float4*>(g_rstd)[c4];
    float4 gm = reinterpret_cast<const float4*>(gamma)[c4];
    float4 bt = reinterpret_cast<const float4*>(beta)[c4];

    float4 ap;
    ap.x = fmaxf((a01.x - mn.x) * rs.x * gm.x + bt.x, 0.f);
    ap.y = fmaxf((a01.y - mn.y) * rs.y * gm.y + bt.y, 0.f);
    ap.z = fmaxf((a23.x - mn.z) * rs.z * gm.z + bt.z, 0.f);
    ap.w = fmaxf((a23.y - mn.w) * rs.w * gm.w + bt.w, 0.f);

    __half2* apst = reinterpret_cast<__half2*>(&g_ap[layer][0]);
    apst[idx * 2]     = __floats2half2_rn(ap.x, ap.y);
    apst[idx * 2 + 1] = __floats2half2_rn(ap.z, ap.w);

    uint2 xraw = reinterpret_cast<const uint2*>(g_xin)[idx];
    float2 x01 = __half22float2(*reinterpret_cast<__half2*>(&xraw.x));
    float2 x23 = __half22float2(*reinterpret_cast<__half2*>(&xraw.y));
    uint2 hraw = reinterpret_cast<const uint2*>(g_a)[idx];
    float2 h01 = __half22float2(*reinterpret_cast<__half2*>(&hraw.x));
    float2 h23 = __half22float2(*reinterpret_cast<__half2*>(&hraw.y));

    float4 hn;
    hn.x = ap.x + 0.2f * x01.x + prevCoef * h01.x;
    hn.y = ap.y + 0.2f * x01.y + prevCoef * h01.y;
    hn.z = ap.z + 0.2f * x23.x + prevCoef * h23.x;
    hn.w = ap.w + 0.2f * x23.y + prevCoef * h23.y;

    uint2 nh;
    *reinterpret_cast<__half2*>(&nh.x) = __floats2half2_rn(hn.x, hn.y);
    *reinterpret_cast<__half2*>(&nh.y) = __floats2half2_rn(hn.z, hn.w);
    reinterpret_cast<uint2*>(g_a)[idx] = nh;
}

// ---------------- output: mix (fused layer-5 BN) + logits + log_softmax ----------------
__global__ void __launch_bounds__(256)
k_output(const float* __restrict__ ow, const float* __restrict__ ob,
         const float* __restrict__ gamma5, const float* __restrict__ beta5,
         float* __restrict__ out)
{
    __shared__ float sw[Hh * 41];
    __shared__ float sb2[Cc];
    __shared__ float srow[8][48];
    __shared__ float smn[Hh], srs[Hh], sg5[Hh], sb5[Hh];
    for (int t = threadIdx.x; t < Hh * Cc; t += 256) {
        int k = t / Cc, c = t % Cc;
        sw[k * 41 + c] = ow[t];
    }
    if (threadIdx.x < Cc) sb2[threadIdx.x] = ob[threadIdx.x];
    {
        int c = threadIdx.x;
        smn[c] = g_mean[c];
        srs[c] = g_rstd[c];
        sg5[c] = gamma5[c];
        sb5[c] = beta5[c];
    }
    __syncthreads();

    float cm[Ll], xc;
#pragma unroll
    for (int l = 0; l < Ll; l++) cm[l] = g_cm[l];
    xc = g_xc;

    int warp = threadIdx.x >> 5, lane = threadIdx.x & 31;
    for (int row = blockIdx.x * 8 + warp; row < Nn; row += gridDim.x * 8) {
        float m[8];
#pragma unroll
        for (int j = 0; j < 8; j++) {
            int col = lane + 32 * j;
            size_t o = (size_t)row * Hh + col;
            float v = xc * __half2float(g_xin[o]);
#pragma unroll
            for (int l = 0; l < Ll - 1; l++)
                v += cm[l] * __half2float(g_ap[l][o]);
            float a5 = __half2float(g_agg[o]);
            float ap5 = fmaxf((a5 - smn[col]) * srs[col] * sg5[col] + sb5[col], 0.f);
            v += cm[Ll - 1] * ap5;
            m[j] = v;
        }
        for (int c = 0; c < Cc; c++) {
            float p = 0.f;
#pragma unroll
            for (int j = 0; j < 8; j++) p += m[j] * sw[(lane + 32 * j) * 41 + c];
#pragma unroll
            for (int off = 16; off > 0; off >>= 1) p += __shfl_xor_sync(0xffffffffu, p, off);
            if (lane == 0) srow[warp][c] = p + sb2[c];
        }
        __syncwarp();
        float v1 = srow[warp][lane];
        float v2 = (lane < 8) ? srow[warp][32 + lane] : -1e30f;
        float mx = fmaxf(v1, v2);
#pragma unroll
        for (int off = 16; off > 0; off >>= 1) mx = fmaxf(mx, __shfl_xor_sync(0xffffffffu, mx, off));
        float s = expf(v1 - mx) + ((lane < 8) ? expf(v2 - mx) : 0.f);
#pragma unroll
        for (int off = 16; off > 0; off >>= 1) s += __shfl_xor_sync(0xffffffffu, s, off);
        float lse = mx + logf(s);
        out[(size_t)row * Cc + lane] = v1 - lse;
        if (lane < 8) out[(size_t)row * Cc + 32 + lane] = v2 - lse;
        __syncwarp();
    }
}

// ---------------- launch ----------------
extern "C" void kernel_launch(void* const* d_in, const int* in_sizes, int n_in,
                              void* d_out, int out_size)
{
    const float* x      = (const float*)d_in[0];
    const int*   ei     = (const int*)d_in[1];
    const float* w_in   = (const float*)d_in[2];
    const float* b_in   = (const float*)d_in[3];
    const float* conv_w = (const float*)d_in[4];
    const float* conv_b = (const float*)d_in[5];
    const float* bn_g   = (const float*)d_in[6];
    const float* bn_b   = (const float*)d_in[7];
    const float* out_w  = (const float*)d_in[8];
    const float* out_b  = (const float*)d_in[9];
    const float* res_w  = (const float*)d_in[10];
    float* out = (float*)d_out;

    (void)in_sizes; (void)n_in; (void)out_size;

    static cudaStream_t s2 = nullptr;
    static cudaEvent_t evFork = nullptr, evJoin = nullptr;
    if (!s2) {
        cudaStreamCreate(&s2);
        cudaEventCreateWithFlags(&evFork, cudaEventDisableTiming);
        cudaEventCreateWithFlags(&evJoin, cudaEventDisableTiming);
        cudaFuncSetAttribute(k_gemm<FIN>, cudaFuncAttributeMaxDynamicSharedMemorySize, SMEM_DYN);
        cudaFuncSetAttribute(k_gemm<Hh>, cudaFuncAttributeMaxDynamicSharedMemorySize, SMEM_DYN);
    }

    __half *p_hw, *p_xin, *p_a, *p_xq, *p_bt;
    cudaGetSymbolAddress((void**)&p_hw, g_hw);
    cudaGetSymbolAddress((void**)&p_xin, g_xin);
    cudaGetSymbolAddress((void**)&p_a, g_a);
    cudaGetSymbolAddress((void**)&p_xq, g_xq);
    cudaGetSymbolAddress((void**)&p_bt, g_bt);

    dim3 gg(4, (Nn + 127) / 128);

    cudaEventRecord(evFork, 0);
    cudaStreamWaitEvent(s2, evFork, 0);

    k_split_x<<<(Nn * FIN + 255) / 256, 256>>>(x);
    k_split_w<<<(Hh * FIN + 255) / 256, 256>>>(w_in, p_bt + BT_IN_OFF, FIN);
    k_split_wconv<<<(Ll * Hh * Hh + 255) / 256, 256>>>(conv_w);
    k_gemm<FIN><<<gg, 256, SMEM_DYN>>>(p_xq, p_bt + BT_IN_OFF, b_in, p_xin, p_a, Nn);

    k_softmax_w<<<1, 1, 0, s2>>>(res_w);
    k_zero_deg<<<(Nn + 255) / 256, 256, 0, s2>>>();
    k_count<<<(Ee + 255) / 256, 256, 0, s2>>>(ei);
    k_dinv<<<(Nn + 255) / 256, 256, 0, s2>>>();
    int nsb = (Nn + 511) / 512;
    k_scan1<<<nsb, 512, 0, s2>>>();
    k_scan2<<<1, 1, 0, s2>>>(nsb);
    k_scan3<<<nsb, 512, 0, s2>>>();
    k_scatter<<<(Ee + 255) / 256, 256, 0, s2>>>(ei);
    cudaEventRecord(evJoin, s2);
    cudaStreamWaitEvent(0, evJoin, 0);

    for (int l = 0; l < Ll; l++) {
        k_gemm<Hh><<<gg, 256, SMEM_DYN>>>(p_a, p_bt + BT_CONV_OFF + (size_t)l * Hh * Hh,
                                          nullptr, p_hw, nullptr, Nn);
        k_aggregate<<<(Nn + 7) / 8, 256>>>(p_hw, conv_b + (size_t)l * Hh, l);
        if (l < Ll - 1)
            k_bnapply<<<(Nn * (Hh / 4) + 255) / 256, 256>>>(bn_g + (size_t)l * Hh,
                                                            bn_b + (size_t)l * Hh,
                                                            l, (l == 0) ? 0.0f : 0.7f);
    }

    k_output<<<1563, 256>>>(out_w, out_b, bn_g + (size_t)(Ll - 1) * Hh,
                            bn_b + (size_t)(Ll - 1) * Hh, out);
}

// round 17
// speedup vs baseline: 1.6248x; 1.6248x over previous
#include <cuda_runtime.h>
#include <cuda_bf16.h>
#include <cuda_fp16.h>
#include <math.h>
#include <stdint.h>

#define Nn 100000
#define Ee 300000
#define Hh 256
#define Cc 40
#define Ll 6
#define FIN 128
#define BN_EPS 1e-5f

// ---------------- device scratch ----------------
__device__ __half g_hw[Nn * Hh];
__device__ __half g_agg[Nn * Hh];
__device__ __half g_xin[Nn * Hh];
__device__ __half g_ap[Ll - 1][Nn * Hh];
__device__ __half g_a[Nn * Hh];
__device__ __half g_xq[Nn * FIN];
#define BT_IN_OFF 0
#define BT_CONV_OFF (Hh * FIN)
__device__ __half g_bt[Hh * FIN + Ll * Hh * Hh];
__device__ float g_dinv[Nn];
__device__ int   g_deg[Nn];
__device__ int   g_cursor[Nn];
__device__ int   g_rowoff[Nn + 1];
__device__ int2  g_csr[Ee];
__device__ double g_bsum[Ll][Hh];
__device__ double g_bsq[Ll][Hh];
__device__ int    g_aggdone[Ll];
__device__ float g_mean[Hh];
__device__ float g_rstd[Hh];
__device__ float g_cm[Ll];
__device__ float g_xc;
__device__ int   g_bsums_scan[256];

// ---------------- helpers ----------------
__device__ __forceinline__ uint32_t smem_u32(const void* p) {
    uint32_t a;
    asm("{ .reg .u64 t; cvta.to.shared.u64 t, %1; cvt.u32.u64 %0, t; }" : "=r"(a) : "l"(p));
    return a;
}
__device__ __forceinline__ void cpasync16(uint32_t dst, const void* src, int szbytes) {
    asm volatile("cp.async.cg.shared.global [%0], [%1], 16, %2;"
                 :: "r"(dst), "l"(src), "r"(szbytes) : "memory");
}
#define CP_COMMIT() asm volatile("cp.async.commit_group;" ::: "memory")
#define CP_WAIT(n)  asm volatile("cp.async.wait_group %0;" :: "n"(n) : "memory")

__device__ __forceinline__ void ldsm4(uint32_t& r0, uint32_t& r1, uint32_t& r2, uint32_t& r3, uint32_t addr) {
    asm volatile("ldmatrix.sync.aligned.m8n8.x4.shared.b16 {%0,%1,%2,%3}, [%4];"
                 : "=r"(r0), "=r"(r1), "=r"(r2), "=r"(r3) : "r"(addr));
}
__device__ __forceinline__ void mma_f16(float c[4], const uint32_t a[4], uint32_t b0, uint32_t b1) {
    asm volatile("mma.sync.aligned.m16n8k16.row.col.f32.f16.f16.f32 "
                 "{%0,%1,%2,%3}, {%4,%5,%6,%7}, {%8,%9}, {%0,%1,%2,%3};"
                 : "+f"(c[0]), "+f"(c[1]), "+f"(c[2]), "+f"(c[3])
                 : "r"(a[0]), "r"(a[1]), "r"(a[2]), "r"(a[3]), "r"(b0), "r"(b1));
}

// ---------------- fp16 GEMM, 3 CTAs/SM, compile-time K ----------------
#define ST_SZ   12288
#define SM_B    8192
#define SMEM_DYN (3 * ST_SZ)

template<int KK>
__global__ void __launch_bounds__(256, 3)
k_gemm(const __half* __restrict__ A, const __half* __restrict__ B,
       const float* __restrict__ bias, __half* __restrict__ C,
       __half* __restrict__ C2, int M)
{
    extern __shared__ char smem[];
    uint32_t sb = smem_u32(smem);
    int tid = threadIdx.x;
    int lane = tid & 31, wid = tid >> 5;
    int wm = wid >> 1, wn = wid & 1;
    int row0 = blockIdx.y * 128;
    int nb0 = blockIdx.x * 64;
    constexpr int nc = KK >> 5;

    const char* AC = (const char*)A;
    const char* BC = (const char*)B;

    float c[2][4][4];
#pragma unroll
    for (int mt = 0; mt < 2; mt++)
#pragma unroll
        for (int nt = 0; nt < 4; nt++)
#pragma unroll
            for (int j = 0; j < 4; j++) c[mt][nt][j] = 0.f;

    auto stage_load = [&](int s, int kc) {
        uint32_t so = sb + s * ST_SZ;
#pragma unroll
        for (int j = 0; j < 2; j++) {
            int flat = tid + j * 256;
            int row = flat >> 2, cq = flat & 3;
            int grow = row0 + row;
            int sz = (grow < M) ? 16 : 0;
            int gc = (grow < M) ? grow : (M - 1);
            size_t srcoff = ((size_t)gc * KK + kc * 32 + cq * 8) * 2;
            uint32_t dst = so + row * 64 + ((cq ^ ((row >> 1) & 3)) << 4);
            cpasync16(dst, AC + srcoff, sz);
        }
        {
            int n = tid >> 2, cq = tid & 3;
            size_t srcoff = ((size_t)(nb0 + n) * KK + kc * 32 + cq * 8) * 2;
            uint32_t dst = so + SM_B + n * 64 + ((cq ^ ((n >> 1) & 3)) << 4);
            cpasync16(dst, BC + srcoff, 16);
        }
    };

    stage_load(0, 0);
    CP_COMMIT();
    if (nc > 1) { stage_load(1, 1); CP_COMMIT(); }

    for (int kc = 0; kc < nc; kc++) {
        if (kc + 2 < nc) {
            stage_load((kc + 2) % 3, kc + 2);
            CP_COMMIT();
            CP_WAIT(2);
        } else {
            CP_WAIT(0);
        }
        __syncthreads();

        uint32_t so = sb + (kc % 3) * ST_SZ;
#pragma unroll
        for (int ks = 0; ks < 2; ks++) {
            uint32_t ah[2][4];
#pragma unroll
            for (int mt = 0; mt < 2; mt++) {
                int ml = wm * 32 + mt * 16 + (lane & 7) + ((lane >> 3) & 1) * 8;
                int ck = 2 * ks + (lane >> 4);
                uint32_t ab = so + ml * 64 + ((ck ^ ((ml >> 1) & 3)) << 4);
                ldsm4(ah[mt][0], ah[mt][1], ah[mt][2], ah[mt][3], ab);
            }
            uint32_t bh[2][4];
#pragma unroll
            for (int j = 0; j < 2; j++) {
                int nl = wn * 32 + j * 16 + (lane & 7) + ((lane >> 4) << 3);
                int ck = 2 * ks + ((lane >> 3) & 1);
                uint32_t bb = so + SM_B + nl * 64 + ((ck ^ ((nl >> 1) & 3)) << 4);
                ldsm4(bh[j][0], bh[j][1], bh[j][2], bh[j][3], bb);
            }
#pragma unroll
            for (int j = 0; j < 2; j++) {
                int nb = j * 2;
#pragma unroll
                for (int mt = 0; mt < 2; mt++) {
                    mma_f16(c[mt][nb + 0], ah[mt], bh[j][0], bh[j][1]);
                    mma_f16(c[mt][nb + 1], ah[mt], bh[j][2], bh[j][3]);
                }
            }
        }
        __syncthreads();
    }

#pragma unroll
    for (int mt = 0; mt < 2; mt++) {
        int r = row0 + wm * 32 + mt * 16 + (lane >> 2);
#pragma unroll
        for (int nt = 0; nt < 4; nt++) {
            int col = nb0 + wn * 32 + nt * 8 + ((lane & 3) << 1);
            float v0 = c[mt][nt][0], v1 = c[mt][nt][1];
            float v2 = c[mt][nt][2], v3 = c[mt][nt][3];
            if (bias) {
                float b0 = bias[col], b1 = bias[col + 1];
                v0 += b0; v1 += b1; v2 += b0; v3 += b1;
            }
            if (r < M) {
                size_t o = (size_t)r * Hh + col;
                __half2 hv = __floats2half2_rn(v0, v1);
                *reinterpret_cast<__half2*>(&C[o]) = hv;
                if (C2) *reinterpret_cast<__half2*>(&C2[o]) = hv;
            }
            if (r + 8 < M) {
                size_t o = (size_t)(r + 8) * Hh + col;
                __half2 hv = __floats2half2_rn(v2, v3);
                *reinterpret_cast<__half2*>(&C[o]) = hv;
                if (C2) *reinterpret_cast<__half2*>(&C2[o]) = hv;
            }
        }
    }
}

// ---------------- splits ----------------
__global__ void k_split_w(const float* __restrict__ W, __half* __restrict__ dst, int K)
{
    int idx = blockIdx.x * 256 + threadIdx.x;
    if (idx >= Hh * K) return;
    int n = idx / K, k = idx - n * K;
    dst[idx] = __float2half(W[(size_t)k * Hh + n]);
}

__global__ void k_split_wconv(const float* __restrict__ W)
{
    int idx = blockIdx.x * 256 + threadIdx.x;
    if (idx >= Ll * Hh * Hh) return;
    int l = idx >> 16;
    int r = idx & 65535;
    int n = r >> 8, k = r & 255;
    g_bt[BT_CONV_OFF + idx] = __float2half(W[(size_t)l * Hh * Hh + (size_t)k * Hh + n]);
}

__global__ void k_split_x(const float* __restrict__ x)
{
    int idx = blockIdx.x * 256 + threadIdx.x;
    if (idx >= Nn * FIN) return;
    g_xq[idx] = __float2half(x[idx]);
}

// ---------------- setup kernels ----------------
__global__ void k_zero_deg() {
    int i = blockIdx.x * blockDim.x + threadIdx.x;
    if (i < Nn) { g_deg[i] = 0; g_cursor[i] = 0; }
}
__global__ void k_count(const int* __restrict__ ei) {
    int e = blockIdx.x * blockDim.x + threadIdx.x;
    if (e < Ee) atomicAdd(&g_deg[ei[Ee + e]], 1);
}
__global__ void k_dinv() {
    int i = blockIdx.x * blockDim.x + threadIdx.x;
    if (i < Nn) g_dinv[i] = rsqrtf((float)(g_deg[i] + 1));
}
__global__ void k_scan1() {
    __shared__ int s[512];
    int i = blockIdx.x * 512 + threadIdx.x;
    int v = (i < Nn) ? g_deg[i] : 0;
    s[threadIdx.x] = v;
    __syncthreads();
    int x = v;
#pragma unroll
    for (int off = 1; off < 512; off <<= 1) {
        int t = (threadIdx.x >= off) ? s[threadIdx.x - off] : 0;
        __syncthreads();
        x += t;
        s[threadIdx.x] = x;
        __syncthreads();
    }
    if (i < Nn) g_rowoff[i] = x - v;
    if (threadIdx.x == 511) g_bsums_scan[blockIdx.x] = x;
}
__global__ void k_scan2(int nb) {
    int acc = 0;
    for (int b = 0; b < nb; b++) { int t = g_bsums_scan[b]; g_bsums_scan[b] = acc; acc += t; }
    g_rowoff[Nn] = acc;
}
__global__ void k_scan3() {
    int i = blockIdx.x * 512 + threadIdx.x;
    if (i < Nn) g_rowoff[i] += g_bsums_scan[blockIdx.x];
}
__global__ void k_scatter(const int* __restrict__ ei) {
    int e = blockIdx.x * blockDim.x + threadIdx.x;
    if (e < Ee) {
        int s = ei[e];
        int d = ei[Ee + e];
        int pos = g_rowoff[d] + atomicAdd(&g_cursor[d], 1);
        float nr = g_dinv[s] * g_dinv[d];
        g_csr[pos] = make_int2(s, __float_as_int(nr));
    }
}
__global__ void k_softmax_w(const float* __restrict__ rw) {
    float mx = -1e30f;
    for (int l = 0; l < Ll; l++) mx = fmaxf(mx, rw[l]);
    float s = 0.f;
    float w[Ll];
    for (int l = 0; l < Ll; l++) { w[l] = expf(rw[l] - mx); s += w[l]; }
    for (int l = 0; l < Ll; l++) w[l] /= s;
    float csum = 0.f;
    for (int m = 0; m < Ll; m++) {
        float c = 0.f, p = 1.f;
        for (int l = m; l < Ll; l++) { c += w[l] * p; p *= 0.7f; }
        g_cm[m] = c;
        csum += c;
    }
    g_xc = 0.2f * csum;
}

// ---------------- aggregation (round-14 proven: 4 nodes/warp, fp32 FFMA, int2) ----------------
__global__ void __launch_bounds__(256)
k_aggregate(const __half* __restrict__ hw, const float* __restrict__ cb, int layer)
{
    __shared__ float ssum[Hh], ssq[Hh];
    ssum[threadIdx.x] = 0.f;
    ssq[threadIdx.x] = 0.f;
    __syncthreads();

    int warp = threadIdx.x >> 5, lane = threadIdx.x & 31;
    float tsum[8], tsq[8];
#pragma unroll
    for (int k = 0; k < 8; k++) { tsum[k] = 0.f; tsq[k] = 0.f; }

    float cbv[8];
#pragma unroll
    for (int j = 0; j < 4; j++) {
        int col = 2 * (lane + 32 * j);
        cbv[2 * j] = cb[col];
        cbv[2 * j + 1] = cb[col + 1];
    }

    int base = (blockIdx.x * 8 + warp) * 4;
    for (int n = 0; n < 4; n++) {
        int i = base + n;
        if (i >= Nn) break;
        float di = g_dinv[i];
        float wself = di * di;
        const __half2* hrow = reinterpret_cast<const __half2*>(hw + (size_t)i * Hh);
        float acc[8];
#pragma unroll
        for (int j = 0; j < 4; j++) {
            float2 f = __half22float2(hrow[lane + 32 * j]);
            acc[2 * j] = wself * f.x;
            acc[2 * j + 1] = wself * f.y;
        }
        int e0 = g_rowoff[i], e1 = g_rowoff[i + 1];
        for (int e = e0; e < e1; e++) {
            int2 p = g_csr[e];
            int s = p.x;
            float nr = __int_as_float(p.y);
            const __half2* srow = reinterpret_cast<const __half2*>(hw + (size_t)s * Hh);
#pragma unroll
            for (int j = 0; j < 4; j++) {
                float2 f = __half22float2(srow[lane + 32 * j]);
                acc[2 * j] += nr * f.x;
                acc[2 * j + 1] += nr * f.y;
            }
        }
        __half2* arow = reinterpret_cast<__half2*>(g_agg + (size_t)i * Hh);
#pragma unroll
        for (int j = 0; j < 4; j++) {
            float v0 = acc[2 * j] + cbv[2 * j];
            float v1 = acc[2 * j + 1] + cbv[2 * j + 1];
            arow[lane + 32 * j] = __floats2half2_rn(v0, v1);
            tsum[2 * j] += v0;  tsq[2 * j] += v0 * v0;
            tsum[2 * j + 1] += v1;  tsq[2 * j + 1] += v1 * v1;
        }
    }
#pragma unroll
    for (int j = 0; j < 4; j++) {
        int col = 2 * (lane + 32 * j);
        atomicAdd(&ssum[col], tsum[2 * j]);
        atomicAdd(&ssq[col], tsq[2 * j]);
        atomicAdd(&ssum[col + 1], tsum[2 * j + 1]);
        atomicAdd(&ssq[col + 1], tsq[2 * j + 1]);
    }
    __syncthreads();
    atomicAdd(&g_bsum[layer][threadIdx.x], (double)ssum[threadIdx.x]);
    atomicAdd(&g_bsq[layer][threadIdx.x], (double)ssq[threadIdx.x]);
    __threadfence();
    __syncthreads();

    __shared__ int isLast;
    if (threadIdx.x == 0)
        isLast = (atomicAdd(&g_aggdone[layer], 1) == (int)gridDim.x - 1);
    __syncthreads();
    if (isLast) {
        __threadfence();
        int c = threadIdx.x;
        double m = g_bsum[layer][c] / (double)Nn;
        double v = g_bsq[layer][c] / (double)Nn - m * m;
        g_mean[c] = (float)m;
        g_rstd[c] = (float)(1.0 / sqrt(v + (double)BN_EPS));
        g_bsum[layer][c] = 0.0;
        g_bsq[layer][c] = 0.0;
        if (c == 0) g_aggdone[layer] = 0;
    }
}

// ---------------- BN + ReLU + residual (layers 0..4) ----------------
__global__ void __launch_bounds__(256)
k_bnapply(const float* __restrict__ gamma, const float* __restrict__ beta,
          int layer, float prevCoef)
{
    int idx = blockIdx.x * blockDim.x + threadIdx.x;
    if (idx >= Nn * (Hh / 4)) return;
    int c4 = (idx & 63);
    uint2 araw = reinterpret_cast<const uint2*>(g_agg)[idx];
    float2 a01 = __half22float2(*reinterpret_cast<__half2*>(&araw.x));
    float2 a23 = __half22float2(*reinterpret_cast<__half2*>(&araw.y));
    float4 mn = reinterpret_cast<const float4*>(g_mean)[c4];
    float4 rs = reinterpret_cast<const float4*>(g_rstd)[c4];
    float4 gm = reinterpret_cast<const float4*>(gamma)[c4];
    float4 bt = reinterpret_cast<const float4*>(beta)[c4];

    float4 ap;
    ap.x = fmaxf((a01.x - mn.x) * rs.x * gm.x + bt.x, 0.f);
    ap.y = fmaxf((a01.y - mn.y) * rs.y * gm.y + bt.y, 0.f);
    ap.z = fmaxf((a23.x - mn.z) * rs.z * gm.z + bt.z, 0.f);
    ap.w = fmaxf((a23.y - mn.w) * rs.w * gm.w + bt.w, 0.f);

    __half2* apst = reinterpret_cast<__half2*>(&g_ap[layer][0]);
    apst[idx * 2]     = __floats2half2_rn(ap.x, ap.y);
    apst[idx * 2 + 1] = __floats2half2_rn(ap.z, ap.w);

    uint2 xraw = reinterpret_cast<const uint2*>(g_xin)[idx];
    float2 x01 = __half22float2(*reinterpret_cast<__half2*>(&xraw.x));
    float2 x23 = __half22float2(*reinterpret_cast<__half2*>(&xraw.y));
    uint2 hraw = reinterpret_cast<const uint2*>(g_a)[idx];
    float2 h01 = __half22float2(*reinterpret_cast<__half2*>(&hraw.x));
    float2 h23 = __half22float2(*reinterpret_cast<__half2*>(&hraw.y));

    float4 hn;
    hn.x = ap.x + 0.2f * x01.x + prevCoef * h01.x;
    hn.y = ap.y + 0.2f * x01.y + prevCoef * h01.y;
    hn.z = ap.z + 0.2f * x23.x + prevCoef * h23.x;
    hn.w = ap.w + 0.2f * x23.y + prevCoef * h23.y;

    uint2 nh;
    *reinterpret_cast<__half2*>(&nh.x) = __floats2half2_rn(hn.x, hn.y);
    *reinterpret_cast<__half2*>(&nh.y) = __floats2half2_rn(hn.z, hn.w);
    reinterpret_cast<uint2*>(g_a)[idx] = nh;
}

// ---------------- output: mix (fused layer-5 BN) + logits + log_softmax ----------------
__global__ void __launch_bounds__(256)
k_output(const float* __restrict__ ow, const float* __restrict__ ob,
         const float* __restrict__ gamma5, const float* __restrict__ beta5,
         float* __restrict__ out)
{
    __shared__ float sw[Hh * 41];
    __shared__ float sb2[Cc];
    __shared__ float srow[8][48];
    __shared__ float smn[Hh], srs[Hh], sg5[Hh], sb5[Hh];
    for (int t = threadIdx.x; t < Hh * Cc; t += 256) {
        int k = t / Cc, c = t % Cc;
        sw[k * 41 + c] = ow[t];
    }
    if (threadIdx.x < Cc) sb2[threadIdx.x] = ob[threadIdx.x];
    {
        int c = threadIdx.x;
        smn[c] = g_mean[c];
        srs[c] = g_rstd[c];
        sg5[c] = gamma5[c];
        sb5[c] = beta5[c];
    }
    __syncthreads();

    float cm[Ll], xc;
#pragma unroll
    for (int l = 0; l < Ll; l++) cm[l] = g_cm[l];
    xc = g_xc;

    int warp = threadIdx.x >> 5, lane = threadIdx.x & 31;
    for (int row = blockIdx.x * 8 + warp; row < Nn; row += gridDim.x * 8) {
        float m[8];
#pragma unroll
        for (int j = 0; j < 8; j++) {
            int col = lane + 32 * j;
            size_t o = (size_t)row * Hh + col;
            float v = xc * __half2float(g_xin[o]);
#pragma unroll
            for (int l = 0; l < Ll - 1; l++)
                v += cm[l] * __half2float(g_ap[l][o]);
            float a5 = __half2float(g_agg[o]);
            float ap5 = fmaxf((a5 - smn[col]) * srs[col] * sg5[col] + sb5[col], 0.f);
            v += cm[Ll - 1] * ap5;
            m[j] = v;
        }
        for (int c = 0; c < Cc; c++) {
            float p = 0.f;
#pragma unroll
            for (int j = 0; j < 8; j++) p += m[j] * sw[(lane + 32 * j) * 41 + c];
#pragma unroll
            for (int off = 16; off > 0; off >>= 1) p += __shfl_xor_sync(0xffffffffu, p, off);
            if (lane == 0) srow[warp][c] = p + sb2[c];
        }
        __syncwarp();
        float v1 = srow[warp][lane];
        float v2 = (lane < 8) ? srow[warp][32 + lane] : -1e30f;
        float mx = fmaxf(v1, v2);
#pragma unroll
        for (int off = 16; off > 0; off >>= 1) mx = fmaxf(mx, __shfl_xor_sync(0xffffffffu, mx, off));
        float s = expf(v1 - mx) + ((lane < 8) ? expf(v2 - mx) : 0.f);
#pragma unroll
        for (int off = 16; off > 0; off >>= 1) s += __shfl_xor_sync(0xffffffffu, s, off);
        float lse = mx + logf(s);
        out[(size_t)row * Cc + lane] = v1 - lse;
        if (lane < 8) out[(size_t)row * Cc + 32 + lane] = v2 - lse;
        __syncwarp();
    }
}

// ---------------- launch ----------------
extern "C" void kernel_launch(void* const* d_in, const int* in_sizes, int n_in,
                              void* d_out, int out_size)
{
    const float* x      = (const float*)d_in[0];
    const int*   ei     = (const int*)d_in[1];
    const float* w_in   = (const float*)d_in[2];
    const float* b_in   = (const float*)d_in[3];
    const float* conv_w = (const float*)d_in[4];
    const float* conv_b = (const float*)d_in[5];
    const float* bn_g   = (const float*)d_in[6];
    const float* bn_b   = (const float*)d_in[7];
    const float* out_w  = (const float*)d_in[8];
    const float* out_b  = (const float*)d_in[9];
    const float* res_w  = (const float*)d_in[10];
    float* out = (float*)d_out;

    (void)in_sizes; (void)n_in; (void)out_size;

    static cudaStream_t s2 = nullptr;
    static cudaEvent_t evFork = nullptr, evJoin = nullptr;
    if (!s2) {
        cudaStreamCreate(&s2);
        cudaEventCreateWithFlags(&evFork, cudaEventDisableTiming);
        cudaEventCreateWithFlags(&evJoin, cudaEventDisableTiming);
        cudaFuncSetAttribute(k_gemm<FIN>, cudaFuncAttributeMaxDynamicSharedMemorySize, SMEM_DYN);
        cudaFuncSetAttribute(k_gemm<Hh>, cudaFuncAttributeMaxDynamicSharedMemorySize, SMEM_DYN);
    }

    __half *p_hw, *p_xin, *p_a, *p_xq, *p_bt;
    cudaGetSymbolAddress((void**)&p_hw, g_hw);
    cudaGetSymbolAddress((void**)&p_xin, g_xin);
    cudaGetSymbolAddress((void**)&p_a, g_a);
    cudaGetSymbolAddress((void**)&p_xq, g_xq);
    cudaGetSymbolAddress((void**)&p_bt, g_bt);

    dim3 gg(4, (Nn + 127) / 128);

    cudaEventRecord(evFork, 0);
    cudaStreamWaitEvent(s2, evFork, 0);

    k_split_x<<<(Nn * FIN + 255) / 256, 256>>>(x);
    k_split_w<<<(Hh * FIN + 255) / 256, 256>>>(w_in, p_bt + BT_IN_OFF, FIN);
    k_split_wconv<<<(Ll * Hh * Hh + 255) / 256, 256>>>(conv_w);
    k_gemm<FIN><<<gg, 256, SMEM_DYN>>>(p_xq, p_bt + BT_IN_OFF, b_in, p_xin, p_a, Nn);

    k_softmax_w<<<1, 1, 0, s2>>>(res_w);
    k_zero_deg<<<(Nn + 255) / 256, 256, 0, s2>>>();
    k_count<<<(Ee + 255) / 256, 256, 0, s2>>>(ei);
    k_dinv<<<(Nn + 255) / 256, 256, 0, s2>>>();
    int nsb = (Nn + 511) / 512;
    k_scan1<<<nsb, 512, 0, s2>>>();
    k_scan2<<<1, 1, 0, s2>>>(nsb);
    k_scan3<<<nsb, 512, 0, s2>>>();
    k_scatter<<<(Ee + 255) / 256, 256, 0, s2>>>(ei);
    cudaEventRecord(evJoin, s2);
    cudaStreamWaitEvent(0, evJoin, 0);

    for (int l = 0; l < Ll; l++) {
        k_gemm<Hh><<<gg, 256, SMEM_DYN>>>(p_a, p_bt + BT_CONV_OFF + (size_t)l * Hh * Hh,
                                          nullptr, p_hw, nullptr, Nn);
        k_aggregate<<<(Nn + 31) / 32, 256>>>(p_hw, conv_b + (size_t)l * Hh, l);
        if (l < Ll - 1)
            k_bnapply<<<(Nn * (Hh / 4) + 255) / 256, 256>>>(bn_g + (size_t)l * Hh,
                                                            bn_b + (size_t)l * Hh,
                                                            l, (l == 0) ? 0.0f : 0.7f);
    }

    k_output<<<1563, 256>>>(out_w, out_b, bn_g + (size_t)(Ll - 1) * Hh,
                            bn_b + (size_t)(Ll - 1) * Hh, out);
}